// round 8
// baseline (speedup 1.0000x reference)
#include <cuda_runtime.h>
#include <cuda_bf16.h>

#define N_NODES 100000
#define N_EDGES 1600000
#define CIN 16
#define HID 32
#define NHID 8

// ---------------- scratch (static device globals: no allocation allowed) ----------------
__device__ float              g_raw[N_EDGES];   // raw mlp out, then exp() in-place
__device__ unsigned           g_menc[N_NODES];  // order-encoded float max for softmax
__device__ float              g_sum[N_NODES];   // softmax denominator
__device__ unsigned long long g_pk0[N_NODES];   // packed (score_bits<<32)|(~eid), src side
__device__ unsigned long long g_pk1[N_NODES];   // dst side
__device__ int                g_maxidx[N_NODES];
__device__ unsigned char      g_rm[N_NODES];
__device__ unsigned char      g_nodes[N_NODES];
__device__ unsigned char      g_edges[N_EDGES];
__device__ int                g_count;
__device__ int                g_done;

// ---------------- f32x2 packed helpers (Blackwell) ----------------
__device__ __forceinline__ unsigned long long pk2(float a, float b) {
    unsigned long long r;
    asm("mov.b64 %0, {%1, %2};" : "=l"(r) : "f"(a), "f"(b));
    return r;
}
__device__ __forceinline__ void upk2(unsigned long long v, float& a, float& b) {
    asm("mov.b64 {%0, %1}, %2;" : "=f"(a), "=f"(b) : "l"(v));
}
__device__ __forceinline__ unsigned long long fma2(unsigned long long a, unsigned long long b,
                                                   unsigned long long c) {
    unsigned long long d;
    asm("fma.rn.f32x2 %0, %1, %2, %3;" : "=l"(d) : "l"(a), "l"(b), "l"(c));
    return d;
}
__device__ __forceinline__ unsigned long long relu2(unsigned long long v) {
    float a, b; upk2(v, a, b);
    a = fmaxf(a, 0.0f); b = fmaxf(b, 0.0f);
    return pk2(a, b);
}

// monotone float<->uint encoding for atomicMax over mixed-sign floats
__device__ __forceinline__ unsigned encf(float f) {
    unsigned b = __float_as_uint(f);
    return (b & 0x80000000u) ? ~b : (b | 0x80000000u);
}
__device__ __forceinline__ float decf(unsigned u) {
    return __uint_as_float((u & 0x80000000u) ? (u & 0x7FFFFFFFu) : ~u);
}

// ---------------- init ----------------
__global__ void k_init() {
    int e = blockIdx.x * blockDim.x + threadIdx.x;
    if (e < N_EDGES) g_edges[e] = 1;
    if (e < N_NODES) {
        g_nodes[e] = 1;
        g_menc[e]  = 0u;
        g_sum[e]   = 0.0f;
        g_pk0[e]   = 0ull;
        g_pk1[e]   = 0ull;
        g_rm[e]    = 0;
    }
    if (e == 0) { g_done = 0; g_count = 0; }
}

// ---------------- edge MLP (2 edges / thread, packed f32x2) ----------------
#define SMEM_ULLS (NHID * HID * HID + NHID * HID + HID)

__global__ __launch_bounds__(128) void k_mlp(
    const float* __restrict__ x, const int* __restrict__ ei,
    const float* __restrict__ Wh, const float* __restrict__ bh,
    const float* __restrict__ Wo, const float* __restrict__ bo)
{
    extern __shared__ unsigned long long sm[];
    unsigned long long* sW  = sm;                          // [NHID*HID*HID] duplicated pairs
    unsigned long long* sB  = sm + NHID * HID * HID;       // [NHID*HID]
    unsigned long long* sWo = sB + NHID * HID;             // [HID]

    for (int i = threadIdx.x; i < NHID * HID * HID; i += blockDim.x) {
        float w = Wh[i]; sW[i] = pk2(w, w);
    }
    for (int i = threadIdx.x; i < NHID * HID; i += blockDim.x) {
        float w = bh[i]; sB[i] = pk2(w, w);
    }
    if (threadIdx.x < HID) { float w = Wo[threadIdx.x]; sWo[threadIdx.x] = pk2(w, w); }
    __syncthreads();

    const float bout = bo[0];
    const int* src = ei;
    const int* dst = ei + N_EDGES;
    const float4* x4 = (const float4*)x;
    const int npairs = N_EDGES / 2;

    for (int p = blockIdx.x * blockDim.x + threadIdx.x; p < npairs;
         p += gridDim.x * blockDim.x) {
        int e0 = 2 * p, e1 = e0 + 1;
        int s0 = src[e0], s1 = src[e1], d0 = dst[e0], d1 = dst[e1];

        unsigned long long h[HID];
        #pragma unroll
        for (int q = 0; q < 4; q++) {
            float4 va = x4[s0 * 4 + q], vb = x4[s1 * 4 + q];
            h[4 * q + 0] = pk2(va.x, vb.x);
            h[4 * q + 1] = pk2(va.y, vb.y);
            h[4 * q + 2] = pk2(va.z, vb.z);
            h[4 * q + 3] = pk2(va.w, vb.w);
        }
        #pragma unroll
        for (int q = 0; q < 4; q++) {
            float4 va = x4[d0 * 4 + q], vb = x4[d1 * 4 + q];
            h[16 + 4 * q + 0] = pk2(va.x, vb.x);
            h[16 + 4 * q + 1] = pk2(va.y, vb.y);
            h[16 + 4 * q + 2] = pk2(va.z, vb.z);
            h[16 + 4 * q + 3] = pk2(va.w, vb.w);
        }

        for (int L = 0; L < NHID; L++) {
            const unsigned long long* W = sW + L * HID * HID;
            const unsigned long long* B = sB + L * HID;
            unsigned long long acc[HID];
            #pragma unroll
            for (int j = 0; j < HID; j++) acc[j] = B[j];
            #pragma unroll
            for (int k = 0; k < HID; k++) {
                unsigned long long a = h[k];
                const ulonglong2* Wr = (const ulonglong2*)(W + k * HID);
                #pragma unroll
                for (int j2 = 0; j2 < HID / 2; j2++) {
                    ulonglong2 w = Wr[j2];
                    acc[2 * j2]     = fma2(a, w.x, acc[2 * j2]);
                    acc[2 * j2 + 1] = fma2(a, w.y, acc[2 * j2 + 1]);
                }
            }
            #pragma unroll
            for (int j = 0; j < HID; j++) h[j] = relu2(acc[j]);
        }

        unsigned long long r = pk2(bout, bout);
        #pragma unroll
        for (int k = 0; k < HID; k++) r = fma2(h[k], sWo[k], r);
        float r0, r1; upk2(r, r0, r1);
        g_raw[e0] = r0;
        g_raw[e1] = r1;
        atomicMax(&g_menc[d0], encf(r0));
        atomicMax(&g_menc[d1], encf(r1));
    }
}

// ---------------- segment softmax ----------------
__global__ void k_exp(const int* __restrict__ ei) {
    int e = blockIdx.x * blockDim.x + threadIdx.x;
    if (e >= N_EDGES) return;
    int d = ei[N_EDGES + e];
    unsigned u = g_menc[d];
    float m = (u == 0u) ? 0.0f : decf(u);          // isfinite fill = 0 for empty segments
    float ex = expf(g_raw[e] - m);
    g_raw[e] = ex;
    atomicAdd(&g_sum[d], ex);
}

__global__ void k_score(const int* __restrict__ ei, float* __restrict__ out) {
    int e = blockIdx.x * blockDim.x + threadIdx.x;
    if (e >= N_EDGES) return;
    int d = ei[N_EDGES + e];
    out[e] = g_raw[e] / g_sum[d] + 0.5f;           // ADD_SCORE
}

// ---------------- merge loop kernels (score lives in out[0:E]) ----------------
// g_done is ONLY modified by k_done, launched between iterations; during an
// iteration it is stable, so every block of every kernel sees the same value.
//
// Fused segmax+argmin: packed key = (score_bits<<32) | (0xFFFFFFFF - eid).
// Scores >= 0 so float order == unsigned-bits order in the top half; among
// equal scores, larger (0xFFFFFFFF - eid) wins == min eid wins. This is
// bitwise-identical to reference segment_max + segment_min-of-achieving-eid.
__global__ void k_i12(const int* __restrict__ ei, const float* __restrict__ out) {
    if (g_done) return;
    int e = blockIdx.x * blockDim.x + threadIdx.x;
    if (e >= N_EDGES) return;
    unsigned sb = __float_as_uint(out[e]);
    unsigned long long key = ((unsigned long long)sb << 32) | (unsigned)(0xFFFFFFFFu - e);
    atomicMax(&g_pk0[ei[e]], key);
    atomicMax(&g_pk1[ei[N_EDGES + e]], key);
}

__global__ void k_i3(const int* __restrict__ ei) {
    if (g_done) return;
    int n = blockIdx.x * blockDim.x + threadIdx.x;
    if (n == 0) g_count = 0;                       // reset for k_i5 of this iteration
    if (n >= N_NODES) return;
    unsigned long long k0 = g_pk0[n], k1 = g_pk1[n];
    float m0 = __uint_as_float((unsigned)(k0 >> 32));   // empty -> 0 bits -> 0.0f (ref fill)
    float m1 = __uint_as_float((unsigned)(k1 >> 32));
    int mi = 0;
    if (m0 > m1) {
        unsigned a = 0xFFFFFFFFu - (unsigned)(k0 & 0xFFFFFFFFu);
        if (a > N_EDGES - 1) a = N_EDGES - 1;      // ref clip
        mi = ei[N_EDGES + a];                      // dst[am0]
    } else if (m1 > m0) {
        unsigned a = 0xFFFFFFFFu - (unsigned)(k1 & 0xFFFFFFFFu);
        if (a > N_EDGES - 1) a = N_EDGES - 1;
        mi = ei[a];                                // src[am1]
    }
    g_maxidx[n] = mi;
}

__global__ void k_i4(const int* __restrict__ ei) {
    if (g_done) return;
    int e = blockIdx.x * blockDim.x + threadIdx.x;
    if (e >= N_EDGES) return;
    int s = ei[e], d = ei[N_EDGES + e];
    bool match = g_nodes[s] && g_nodes[d] && (g_maxidx[d] == s) && (g_maxidx[s] == d);
    if (match) {
        g_edges[e] = 0;
        g_rm[s] = 1;
        g_rm[d] = 1;
    }
}

__global__ void k_i5() {
    if (g_done) return;
    int n = blockIdx.x * blockDim.x + threadIdx.x;
    bool inb = (n < N_NODES);
    bool alive = false;
    if (inb) {
        alive = g_nodes[n] && !g_rm[n];
        g_nodes[n] = alive ? 1 : 0;
        // reset per-iteration scratch for the next iteration
        g_pk0[n] = 0ull;
        g_pk1[n] = 0ull;
        g_rm[n] = 0;
    }
    unsigned bal = __ballot_sync(0xffffffffu, alive);
    if ((threadIdx.x & 31) == 0 && bal)
        atomicAdd(&g_count, __popc(bal));
}

__global__ void k_i6(const int* __restrict__ ei, float* __restrict__ out) {
    if (g_done) return;
    int e = blockIdx.x * blockDim.x + threadIdx.x;
    if (e >= N_EDGES) return;
    bool keep = g_nodes[ei[e]] && g_nodes[ei[N_EDGES + e]];
    if (!keep) out[e] = 0.0f;
}

// done-commit between iterations: crossing iteration applies fully (matches the
// reference, whose freeze uses the OLD done flag), subsequent iterations skip.
__global__ void k_done() {
    if (!g_done && g_count * 20 <= N_NODES) g_done = 1;   // ratio <= 0.05
}

// ---------------- final bool outputs ----------------
__global__ void k_final(float* __restrict__ out) {
    int e = blockIdx.x * blockDim.x + threadIdx.x;
    if (e < N_EDGES) out[N_EDGES + e] = g_edges[e] ? 1.0f : 0.0f;
    if (e < N_NODES) out[2 * N_EDGES + e] = g_nodes[e] ? 1.0f : 0.0f;
}

// ---------------- launch ----------------
extern "C" void kernel_launch(void* const* d_in, const int* in_sizes, int n_in,
                              void* d_out, int out_size) {
    const float* x  = nullptr;
    const int*   ei = nullptr;
    const float* Wh = nullptr;
    const float* bh = nullptr;
    const float* Wo = nullptr;
    const float* bo = nullptr;
    for (int i = 0; i < n_in; i++) {
        switch (in_sizes[i]) {
            case N_NODES * CIN:     x  = (const float*)d_in[i]; break;
            case 2 * N_EDGES:       ei = (const int*)d_in[i];   break;
            case N_NODES:           /* batch, unused */          break;
            case NHID * HID * HID:  Wh = (const float*)d_in[i]; break;
            case NHID * HID:        bh = (const float*)d_in[i]; break;
            case HID:               Wo = (const float*)d_in[i]; break;
            case 1:                 bo = (const float*)d_in[i]; break;
            default: break;
        }
    }
    float* out = (float*)d_out;

    const int TB = 256;
    const int GE = (N_EDGES + TB - 1) / TB;   // 6250
    const int GN = (N_NODES + TB - 1) / TB;   // 391

    k_init<<<GE, TB>>>();

    static const size_t smem_bytes = (size_t)SMEM_ULLS * sizeof(unsigned long long); // 67,840
    cudaFuncSetAttribute(k_mlp, cudaFuncAttributeMaxDynamicSharedMemorySize, (int)smem_bytes);
    k_mlp<<<444, 128, smem_bytes>>>(x, ei, Wh, bh, Wo, bo);

    k_exp<<<GE, TB>>>(ei);
    k_score<<<GE, TB>>>(ei, out);

    for (int it = 0; it < 10; it++) {
        k_i12<<<GE, TB>>>(ei, out);
        k_i3<<<GN, TB>>>(ei);
        k_i4<<<GE, TB>>>(ei);
        k_i5<<<GN, TB>>>();
        k_i6<<<GE, TB>>>(ei, out);
        k_done<<<1, 1>>>();
    }

    k_final<<<GE, TB>>>(out);
}

// round 15
// speedup vs baseline: 1.0666x; 1.0666x over previous
#include <cuda_runtime.h>
#include <cuda_bf16.h>

#define N_NODES 100000
#define N_EDGES 1600000
#define CIN 16
#define HID 32
#define NHID 8

// ---------------- scratch (static device globals: no allocation allowed) ----------------
__device__ float              g_raw[N_EDGES];     // raw mlp out, then exp() in-place
__device__ unsigned           g_menc[N_NODES];    // order-encoded float max for softmax
__device__ float              g_sum[N_NODES];     // softmax denominator
__device__ unsigned long long g_pk0[N_NODES];     // packed (score_bits<<32)|(~eid), src side
__device__ unsigned long long g_pk1[N_NODES];     // dst side
__device__ int                g_maxidx[N_NODES];
__device__ unsigned char      g_rm[N_NODES];
__device__ unsigned char      g_nodes[N_NODES];
__device__ unsigned char      g_edges[N_EDGES];
__device__ float              g_u[N_NODES * HID]; // per-node x @ W_top   (layer-1 split)
__device__ float              g_v[N_NODES * HID]; // per-node x @ W_bot
__device__ int4               g_recA[N_EDGES];    // active-edge records {e, s, d, score_bits}
__device__ int4               g_recB[N_EDGES];
__device__ int                g_nact[2];
__device__ int                g_count;
__device__ int                g_done;

// ---------------- f32x2 packed helpers (Blackwell) ----------------
__device__ __forceinline__ unsigned long long pk2(float a, float b) {
    unsigned long long r;
    asm("mov.b64 %0, {%1, %2};" : "=l"(r) : "f"(a), "f"(b));
    return r;
}
__device__ __forceinline__ void upk2(unsigned long long v, float& a, float& b) {
    asm("mov.b64 {%0, %1}, %2;" : "=f"(a), "=f"(b) : "l"(v));
}
__device__ __forceinline__ unsigned long long fma2(unsigned long long a, unsigned long long b,
                                                   unsigned long long c) {
    unsigned long long d;
    asm("fma.rn.f32x2 %0, %1, %2, %3;" : "=l"(d) : "l"(a), "l"(b), "l"(c));
    return d;
}
__device__ __forceinline__ unsigned long long relu2(unsigned long long v) {
    float a, b; upk2(v, a, b);
    a = fmaxf(a, 0.0f); b = fmaxf(b, 0.0f);
    return pk2(a, b);
}

// monotone float<->uint encoding for atomicMax over mixed-sign floats
__device__ __forceinline__ unsigned encf(float f) {
    unsigned b = __float_as_uint(f);
    return (b & 0x80000000u) ? ~b : (b | 0x80000000u);
}
__device__ __forceinline__ float decf(unsigned u) {
    return __uint_as_float((u & 0x80000000u) ? (u & 0x7FFFFFFFu) : ~u);
}

// ---------------- init ----------------
__global__ void k_init() {
    int e = blockIdx.x * blockDim.x + threadIdx.x;
    if (e < N_EDGES) g_edges[e] = 1;
    if (e < N_NODES) {
        g_nodes[e] = 1;
        g_menc[e]  = 0u;
        g_sum[e]   = 0.0f;
        g_pk0[e]   = 0ull;
        g_pk1[e]   = 0ull;
        g_rm[e]    = 0;
    }
    if (e == 0) { g_done = 0; g_count = 0; g_nact[0] = 0; g_nact[1] = 0; }
}

// ---------------- per-node layer-1 halves: u = x @ W_top, v = x @ W_bot ----------------
__global__ __launch_bounds__(256) void k_uv(const float* __restrict__ x,
                                            const float* __restrict__ Wh) {
    __shared__ float sw[HID * HID];          // layer 0 weights [2C=32, 32]
    for (int i = threadIdx.x; i < HID * HID; i += blockDim.x) sw[i] = Wh[i];
    __syncthreads();
    int n = blockIdx.x * blockDim.x + threadIdx.x;
    if (n >= N_NODES) return;
    const float4* x4 = (const float4*)x;
    float xr[CIN];
    #pragma unroll
    for (int q = 0; q < 4; q++) {
        float4 t = x4[n * 4 + q];
        xr[4 * q + 0] = t.x; xr[4 * q + 1] = t.y; xr[4 * q + 2] = t.z; xr[4 * q + 3] = t.w;
    }
    float u[HID], v[HID];
    #pragma unroll
    for (int j = 0; j < HID; j++) { u[j] = 0.0f; v[j] = 0.0f; }
    #pragma unroll
    for (int k = 0; k < CIN; k++) {
        float xk = xr[k];
        #pragma unroll
        for (int j = 0; j < HID; j++) {
            u[j] = fmaf(xk, sw[k * HID + j], u[j]);          // rows 0..15  (x_src part)
            v[j] = fmaf(xk, sw[(CIN + k) * HID + j], v[j]);  // rows 16..31 (x_dst part)
        }
    }
    float4* u4 = (float4*)g_u;
    float4* v4 = (float4*)g_v;
    #pragma unroll
    for (int q = 0; q < 8; q++) {
        u4[n * 8 + q] = make_float4(u[4 * q], u[4 * q + 1], u[4 * q + 2], u[4 * q + 3]);
        v4[n * 8 + q] = make_float4(v[4 * q], v[4 * q + 1], v[4 * q + 2], v[4 * q + 3]);
    }
}

// ---------------- edge MLP layers 2..8 + out (2 edges / thread, packed f32x2) ----------------
#define NL2 (NHID - 1)                                 // 7 remaining hidden layers
#define SMEM_ULLS (NL2 * HID * HID + NL2 * HID + HID + HID / 2)

__global__ __launch_bounds__(128) void k_mlp(
    const int* __restrict__ ei,
    const float* __restrict__ Wh, const float* __restrict__ bh,
    const float* __restrict__ Wo, const float* __restrict__ bo)
{
    extern __shared__ unsigned long long sm[];
    unsigned long long* sW  = sm;                      // [NL2*HID*HID] dup pairs (layers 1..7)
    unsigned long long* sB  = sm + NL2 * HID * HID;    // [NL2*HID]
    unsigned long long* sWo = sB + NL2 * HID;          // [HID]
    float* sb0 = (float*)(sWo + HID);                  // [HID] layer-0 bias (plain)

    for (int i = threadIdx.x; i < NL2 * HID * HID; i += blockDim.x) {
        float w = Wh[HID * HID + i]; sW[i] = pk2(w, w);
    }
    for (int i = threadIdx.x; i < NL2 * HID; i += blockDim.x) {
        float w = bh[HID + i]; sB[i] = pk2(w, w);
    }
    if (threadIdx.x < HID) {
        float w = Wo[threadIdx.x]; sWo[threadIdx.x] = pk2(w, w);
        sb0[threadIdx.x] = bh[threadIdx.x];
    }
    __syncthreads();

    const float bout = bo[0];
    const int* src = ei;
    const int* dst = ei + N_EDGES;
    const float4* u4 = (const float4*)g_u;
    const float4* v4 = (const float4*)g_v;
    const int npairs = N_EDGES / 2;

    for (int p = blockIdx.x * blockDim.x + threadIdx.x; p < npairs;
         p += gridDim.x * blockDim.x) {
        int e0 = 2 * p, e1 = e0 + 1;
        int s0 = src[e0], s1 = src[e1], d0 = dst[e0], d1 = dst[e1];

        unsigned long long h[HID];
        #pragma unroll
        for (int q = 0; q < 8; q++) {
            float4 ua = u4[s0 * 8 + q], ub = u4[s1 * 8 + q];
            float4 va = v4[d0 * 8 + q], vb = v4[d1 * 8 + q];
            int j = 4 * q;
            float f0, f1;
            f0 = ua.x + va.x + sb0[j + 0]; f1 = ub.x + vb.x + sb0[j + 0];
            h[j + 0] = pk2(fmaxf(f0, 0.0f), fmaxf(f1, 0.0f));
            f0 = ua.y + va.y + sb0[j + 1]; f1 = ub.y + vb.y + sb0[j + 1];
            h[j + 1] = pk2(fmaxf(f0, 0.0f), fmaxf(f1, 0.0f));
            f0 = ua.z + va.z + sb0[j + 2]; f1 = ub.z + vb.z + sb0[j + 2];
            h[j + 2] = pk2(fmaxf(f0, 0.0f), fmaxf(f1, 0.0f));
            f0 = ua.w + va.w + sb0[j + 3]; f1 = ub.w + vb.w + sb0[j + 3];
            h[j + 3] = pk2(fmaxf(f0, 0.0f), fmaxf(f1, 0.0f));
        }

        for (int L = 0; L < NL2; L++) {
            const unsigned long long* W = sW + L * HID * HID;
            const unsigned long long* B = sB + L * HID;
            unsigned long long acc[HID];
            #pragma unroll
            for (int j = 0; j < HID; j++) acc[j] = B[j];
            #pragma unroll
            for (int k = 0; k < HID; k++) {
                unsigned long long a = h[k];
                const ulonglong2* Wr = (const ulonglong2*)(W + k * HID);
                #pragma unroll
                for (int j2 = 0; j2 < HID / 2; j2++) {
                    ulonglong2 w = Wr[j2];
                    acc[2 * j2]     = fma2(a, w.x, acc[2 * j2]);
                    acc[2 * j2 + 1] = fma2(a, w.y, acc[2 * j2 + 1]);
                }
            }
            #pragma unroll
            for (int j = 0; j < HID; j++) h[j] = relu2(acc[j]);
        }

        unsigned long long r = pk2(bout, bout);
        #pragma unroll
        for (int k = 0; k < HID; k++) r = fma2(h[k], sWo[k], r);
        float r0, r1; upk2(r, r0, r1);
        g_raw[e0] = r0;
        g_raw[e1] = r1;
        atomicMax(&g_menc[d0], encf(r0));
        atomicMax(&g_menc[d1], encf(r1));
    }
}

// ---------------- segment softmax ----------------
__global__ void k_exp(const int* __restrict__ ei) {
    int e = blockIdx.x * blockDim.x + threadIdx.x;
    if (e >= N_EDGES) return;
    int d = ei[N_EDGES + e];
    unsigned u = g_menc[d];
    float m = (u == 0u) ? 0.0f : decf(u);          // isfinite fill = 0 for empty segments
    float ex = expf(g_raw[e] - m);
    g_raw[e] = ex;
    atomicAdd(&g_sum[d], ex);
}

__global__ void k_score(const int* __restrict__ ei, float* __restrict__ out) {
    int e = blockIdx.x * blockDim.x + threadIdx.x;
    if (e >= N_EDGES) return;
    int d = ei[N_EDGES + e];
    out[e] = g_raw[e] / g_sum[d] + 0.5f;           // ADD_SCORE
}

// ---------------- merge loop ----------------
// Invariant: score > 0  <=>  both endpoints alive. Zero-score edges can never win a
// strictly-greater max comparison nor supply an argmax, so iterating only live
// edges (the compact record list) is exactly equivalent to the full pass.
// g_done is ONLY modified by k_done, between iterations.

__global__ void k_i12_full(const int* __restrict__ ei, const float* __restrict__ out) {
    if (g_done) return;
    int e = blockIdx.x * blockDim.x + threadIdx.x;
    if (e >= N_EDGES) return;
    unsigned sb = __float_as_uint(out[e]);
    unsigned long long key = ((unsigned long long)sb << 32) | (unsigned)(0xFFFFFFFFu - e);
    atomicMax(&g_pk0[ei[e]], key);
    atomicMax(&g_pk1[ei[N_EDGES + e]], key);
}

__global__ void k_i12_list(int cur) {
    if (g_done) return;
    int i = blockIdx.x * blockDim.x + threadIdx.x;
    if (i >= g_nact[cur]) return;
    int4 r = cur ? g_recB[i] : g_recA[i];
    unsigned long long key = ((unsigned long long)(unsigned)r.w << 32)
                           | (unsigned)(0xFFFFFFFFu - r.x);
    atomicMax(&g_pk0[r.y], key);
    atomicMax(&g_pk1[r.z], key);
}

__global__ void k_i3(const int* __restrict__ ei, int nxt) {
    if (g_done) return;
    int n = blockIdx.x * blockDim.x + threadIdx.x;
    if (n == 0) { g_count = 0; g_nact[nxt] = 0; }
    if (n >= N_NODES) return;
    unsigned long long k0 = g_pk0[n], k1 = g_pk1[n];
    float m0 = __uint_as_float((unsigned)(k0 >> 32));   // empty -> 0.0f (ref fill)
    float m1 = __uint_as_float((unsigned)(k1 >> 32));
    int mi = 0;
    if (m0 > m1) {
        unsigned a = 0xFFFFFFFFu - (unsigned)(k0 & 0xFFFFFFFFu);
        if (a > N_EDGES - 1) a = N_EDGES - 1;           // ref clip
        mi = ei[N_EDGES + a];                           // dst[am0]
    } else if (m1 > m0) {
        unsigned a = 0xFFFFFFFFu - (unsigned)(k1 & 0xFFFFFFFFu);
        if (a > N_EDGES - 1) a = N_EDGES - 1;
        mi = ei[a];                                     // src[am1]
    }
    g_maxidx[n] = mi;
}

__global__ void k_i4_full(const int* __restrict__ ei) {
    if (g_done) return;
    int e = blockIdx.x * blockDim.x + threadIdx.x;
    if (e >= N_EDGES) return;
    int s = ei[e], d = ei[N_EDGES + e];
    // iteration 0: all nodes alive, no need to check
    if ((g_maxidx[d] == s) && (g_maxidx[s] == d)) {
        g_edges[e] = 0;
        g_rm[s] = 1;
        g_rm[d] = 1;
    }
}

__global__ void k_i4_list(int cur) {
    if (g_done) return;
    int i = blockIdx.x * blockDim.x + threadIdx.x;
    if (i >= g_nact[cur]) return;
    int4 r = cur ? g_recB[i] : g_recA[i];
    // record edges provably have both endpoints alive at this point
    if ((g_maxidx[r.z] == r.y) && (g_maxidx[r.y] == r.z)) {
        g_edges[r.x] = 0;
        g_rm[r.y] = 1;
        g_rm[r.z] = 1;
    }
}

__global__ void k_i5() {
    if (g_done) return;
    int n = blockIdx.x * blockDim.x + threadIdx.x;
    bool alive = false;
    if (n < N_NODES) {
        alive = g_nodes[n] && !g_rm[n];
        g_nodes[n] = alive ? 1 : 0;
        g_pk0[n] = 0ull;
        g_pk1[n] = 0ull;
        g_rm[n] = 0;
    }
    unsigned bal = __ballot_sync(0xffffffffu, alive);
    if ((threadIdx.x & 31) == 0 && bal)
        atomicAdd(&g_count, __popc(bal));
}

__device__ __forceinline__ void append_rec(bool keep, int nxt, int e, int s, int d, unsigned sb) {
    unsigned m = __ballot_sync(0xffffffffu, keep);
    if (!m) return;
    int lane = threadIdx.x & 31;
    int base = 0;
    if (lane == 0) base = atomicAdd(&g_nact[nxt], __popc(m));
    base = __shfl_sync(0xffffffffu, base, 0);
    if (keep) {
        int off = __popc(m & ((1u << lane) - 1u));
        int4 rec = make_int4(e, s, d, (int)sb);
        if (nxt) g_recB[base + off] = rec; else g_recA[base + off] = rec;
    }
}

__global__ void k_i6_full(const int* __restrict__ ei, float* __restrict__ out) {
    if (g_done) return;
    int e = blockIdx.x * blockDim.x + threadIdx.x;
    bool keep = false; int s = 0, d = 0; unsigned sb = 0;
    if (e < N_EDGES) {
        s = ei[e]; d = ei[N_EDGES + e];
        keep = g_nodes[s] && g_nodes[d];
        if (keep) sb = __float_as_uint(out[e]);
        else out[e] = 0.0f;
    }
    append_rec(keep, 1, e, s, d, sb);              // iteration 0 builds list 1
}

__global__ void k_i6_list(int cur, float* __restrict__ out) {
    if (g_done) return;
    int i = blockIdx.x * blockDim.x + threadIdx.x;
    bool keep = false; int4 r = make_int4(0, 0, 0, 0);
    if (i < g_nact[cur]) {
        r = cur ? g_recB[i] : g_recA[i];
        keep = g_nodes[r.y] && g_nodes[r.z];
        if (!keep) out[r.x] = 0.0f;
    }
    append_rec(keep, cur ^ 1, r.x, r.y, r.z, (unsigned)r.w);
}

// done-commit between iterations (crossing iteration applies fully, matching ref)
__global__ void k_done() {
    if (!g_done && g_count * 20 <= N_NODES) g_done = 1;   // ratio <= 0.05
}

// ---------------- final bool outputs ----------------
__global__ void k_final(float* __restrict__ out) {
    int e = blockIdx.x * blockDim.x + threadIdx.x;
    if (e < N_EDGES) out[N_EDGES + e] = g_edges[e] ? 1.0f : 0.0f;
    if (e < N_NODES) out[2 * N_EDGES + e] = g_nodes[e] ? 1.0f : 0.0f;
}

// ---------------- launch ----------------
extern "C" void kernel_launch(void* const* d_in, const int* in_sizes, int n_in,
                              void* d_out, int out_size) {
    const float* x  = nullptr;
    const int*   ei = nullptr;
    const float* Wh = nullptr;
    const float* bh = nullptr;
    const float* Wo = nullptr;
    const float* bo = nullptr;
    for (int i = 0; i < n_in; i++) {
        switch (in_sizes[i]) {
            case N_NODES * CIN:     x  = (const float*)d_in[i]; break;
            case 2 * N_EDGES:       ei = (const int*)d_in[i];   break;
            case N_NODES:           /* batch, unused */          break;
            case NHID * HID * HID:  Wh = (const float*)d_in[i]; break;
            case NHID * HID:        bh = (const float*)d_in[i]; break;
            case HID:               Wo = (const float*)d_in[i]; break;
            case 1:                 bo = (const float*)d_in[i]; break;
            default: break;
        }
    }
    float* out = (float*)d_out;

    const int TB = 256;
    const int GE = (N_EDGES + TB - 1) / TB;   // 6250
    const int GN = (N_NODES + TB - 1) / TB;   // 391

    k_init<<<GE, TB>>>();
    k_uv<<<GN, TB>>>(x, Wh);

    static const size_t smem_bytes = (size_t)SMEM_ULLS * sizeof(unsigned long long);
    cudaFuncSetAttribute(k_mlp, cudaFuncAttributeMaxDynamicSharedMemorySize, (int)smem_bytes);
    k_mlp<<<444, 128, smem_bytes>>>(ei, Wh, bh, Wo, bo);

    k_exp<<<GE, TB>>>(ei);
    k_score<<<GE, TB>>>(ei, out);

    for (int it = 0; it < 10; it++) {
        int cur = it & 1, nxt = cur ^ 1;
        if (it == 0) {
            k_i12_full<<<GE, TB>>>(ei, out);
            k_i3<<<GN, TB>>>(ei, 1);
            k_i4_full<<<GE, TB>>>(ei);
            k_i5<<<GN, TB>>>();
            k_i6_full<<<GE, TB>>>(ei, out);
        } else {
            k_i12_list<<<GE, TB>>>(cur);
            k_i3<<<GN, TB>>>(ei, nxt);
            k_i4_list<<<GE, TB>>>(cur);
            k_i5<<<GN, TB>>>();
            k_i6_list<<<GE, TB>>>(cur, out);
        }
        k_done<<<1, 1>>>();
    }

    k_final<<<GE, TB>>>(out);
}